// round 12
// baseline (speedup 1.0000x reference)
#include <cuda_runtime.h>
#include <cuda_bf16.h>
#include <cstdint>

#define Bb   4
#define Tt   1024
#define EMBD 1024
#define Hh   16
#define HEAD 64
#define BTR  (Bb * Tt)
#define NEG_BIG (-1e30f)

static __device__ float g_Q[(size_t)BTR * EMBD];
static __device__ float g_K[(size_t)BTR * EMBD];
static __device__ float g_V[(size_t)BTR * EMBD];
static __device__ float g_O[(size_t)BTR * EMBD];
static __device__ float g_W[(size_t)Bb * Hh * Tt * Tt];

// prepped bf16 hi/lo (interleaved: hi at row 2r, lo at row 2r+1)
static __device__ __align__(16) __nv_bfloat16 g_xp[2ull * BTR * EMBD];
static __device__ __align__(16) __nv_bfloat16 g_cp[2ull * BTR * EMBD];
static __device__ __align__(16) __nv_bfloat16 g_wqp[2ull * EMBD * EMBD];
static __device__ __align__(16) __nv_bfloat16 g_wkp[2ull * EMBD * EMBD];
static __device__ __align__(16) __nv_bfloat16 g_wvp[2ull * EMBD * EMBD];
static __device__ __align__(16) __nv_bfloat16 g_wop[2ull * EMBD * EMBD];

// ===========================================================================
// helpers
// ===========================================================================
__device__ __forceinline__ uint32_t smem_u32(const void* p) {
    uint32_t a;
    asm("{ .reg .u64 t; cvta.to.shared.u64 t, %1; cvt.u32.u64 %0, t; }" : "=r"(a) : "l"(p));
    return a;
}
__device__ __forceinline__ void ldsm4(uint32_t addr, uint32_t& r0, uint32_t& r1,
                                      uint32_t& r2, uint32_t& r3) {
    asm volatile("ldmatrix.sync.aligned.m8n8.x4.shared.b16 {%0,%1,%2,%3}, [%4];"
                 : "=r"(r0), "=r"(r1), "=r"(r2), "=r"(r3) : "r"(addr));
}
__device__ __forceinline__ void ldsm4t(uint32_t addr, uint32_t& r0, uint32_t& r1,
                                       uint32_t& r2, uint32_t& r3) {
    asm volatile("ldmatrix.sync.aligned.m8n8.x4.trans.shared.b16 {%0,%1,%2,%3}, [%4];"
                 : "=r"(r0), "=r"(r1), "=r"(r2), "=r"(r3) : "r"(addr));
}
__device__ __forceinline__ void mma_bf16(float (&d)[4], const uint32_t (&a)[4],
                                         uint32_t b0, uint32_t b1) {
    asm volatile("mma.sync.aligned.m16n8k16.row.col.f32.bf16.bf16.f32 "
                 "{%0,%1,%2,%3},{%4,%5,%6,%7},{%8,%9},{%0,%1,%2,%3};"
                 : "+f"(d[0]), "+f"(d[1]), "+f"(d[2]), "+f"(d[3])
                 : "r"(a[0]), "r"(a[1]), "r"(a[2]), "r"(a[3]), "r"(b0), "r"(b1));
}
__device__ __forceinline__ void cvt_hilo(float4 v, uint2& hi, uint2& lo) {
    __nv_bfloat162 h0 = __floats2bfloat162_rn(v.x, v.y);
    __nv_bfloat162 h1 = __floats2bfloat162_rn(v.z, v.w);
    float rx = v.x - __bfloat162float(h0.x);
    float ry = v.y - __bfloat162float(h0.y);
    float rz = v.z - __bfloat162float(h1.x);
    float rw = v.w - __bfloat162float(h1.y);
    __nv_bfloat162 l0 = __floats2bfloat162_rn(rx, ry);
    __nv_bfloat162 l1 = __floats2bfloat162_rn(rz, rw);
    hi = make_uint2(*(uint32_t*)&h0, *(uint32_t*)&h1);
    lo = make_uint2(*(uint32_t*)&l0, *(uint32_t*)&l1);
}
__device__ __forceinline__ void pack2(float x, float y, uint32_t& h, uint32_t& l) {
    __nv_bfloat162 hh = __floats2bfloat162_rn(x, y);
    float rx = x - __bfloat162float(hh.x);
    float ry = y - __bfloat162float(hh.y);
    __nv_bfloat162 ll = __floats2bfloat162_rn(rx, ry);
    h = *(uint32_t*)&hh;
    l = *(uint32_t*)&ll;
}

// ===========================================================================
// prep: fp32 matrix -> bf16 hi/lo with interleaved rows (hi=2r, lo=2r+1)
// ===========================================================================
__global__ void __launch_bounds__(256)
prep_all(const float* __restrict__ x, const float* __restrict__ ctx,
         const float* __restrict__ wq, const float* __restrict__ wk,
         const float* __restrict__ wv, const float* __restrict__ wo)
{
    const int z = blockIdx.z;
    const float* srcs[6] = {x, ctx, wq, wk, wv, wo};
    __nv_bfloat16* dsts[6] = {g_xp, g_cp, g_wqp, g_wkp, g_wvp, g_wop};
    const size_t nf4 = (z < 2) ? (size_t)BTR * EMBD / 4 : (size_t)EMBD * EMBD / 4;

    size_t i = (size_t)blockIdx.x * 256 + threadIdx.x;
    if (i >= nf4) return;
    float4 v = ((const float4*)srcs[z])[i];
    uint2 hh, ll;
    cvt_hilo(v, hh, ll);
    size_t r = i >> 8;                 // 256 float4 per 1024-wide row
    size_t c = (i & 255) * 4;
    __nv_bfloat16* d = dsts[z];
    *(uint2*)&d[(2 * r) * EMBD + c]     = hh;
    *(uint2*)&d[(2 * r + 1) * EMBD + c] = ll;
}

// ===========================================================================
// NT GEMM (C = A * B^T), 128x128 block, BK=32, 512 threads / 16 warps,
// bf16 hi/lo 3-pass. B always prepped bf16. APREP: A prepped vs fp32.
// ===========================================================================
#define STR_K  40
#define A_HI_O 0
#define A_LO_O 10240
#define B_HI_O 20480
#define B_LO_O 30720
#define STAGE_NT 40960

template <bool APREP>
__device__ __forceinline__ void nt_body(const float* __restrict__ Af,
                                        const __nv_bfloat16* __restrict__ Ap,
                                        const __nv_bfloat16* __restrict__ Bp,
                                        float* __restrict__ Cb, char* sm,
                                        int m0, int n0)
{
    const int tid = threadIdx.x, lane = tid & 31, wid = tid >> 5;
    const int NC = EMBD / 32;

    float acc[2][4][4] = {};
    float4 laf[2];
    uint4 ua, ual, ub, ubl;

    // indices for prepped fills (one uint4-pair per thread: 8 elems)
    const int prow = tid >> 2, pc8 = (tid & 3) << 3;

    // prologue: stage 0 loads
    if (APREP) {
        ua  = *(const uint4*)&Ap[(size_t)(2 * (m0 + prow)) * EMBD + pc8];
        ual = *(const uint4*)&Ap[(size_t)(2 * (m0 + prow) + 1) * EMBD + pc8];
    } else {
        #pragma unroll
        for (int i = 0; i < 2; i++) {
            int seg = tid + i * 512, row = seg >> 3, c4 = (seg & 7) << 2;
            laf[i] = *(const float4*)&Af[(size_t)(m0 + row) * EMBD + c4];
        }
    }
    ub  = *(const uint4*)&Bp[(size_t)(2 * (n0 + prow)) * EMBD + pc8];
    ubl = *(const uint4*)&Bp[(size_t)(2 * (n0 + prow) + 1) * EMBD + pc8];

    // prologue stores
    {
        uint32_t poff = (uint32_t)(prow * STR_K + pc8) * 2;
        if (APREP) {
            *(uint4*)(sm + A_HI_O + poff) = ua;
            *(uint4*)(sm + A_LO_O + poff) = ual;
        } else {
            #pragma unroll
            for (int i = 0; i < 2; i++) {
                int seg = tid + i * 512, row = seg >> 3, c4 = (seg & 7) << 2;
                uint2 h, l;
                cvt_hilo(laf[i], h, l);
                uint32_t off = (uint32_t)(row * STR_K + c4) * 2;
                *(uint2*)(sm + A_HI_O + off) = h;
                *(uint2*)(sm + A_LO_O + off) = l;
            }
        }
        *(uint4*)(sm + B_HI_O + poff) = ub;
        *(uint4*)(sm + B_LO_O + poff) = ubl;
    }
    __syncthreads();

    const int wm = wid >> 2, wn = wid & 3;
    const int arow = lane & 15, acol8 = (lane >> 4) << 3;
    const int brow = (lane & 7) + ((lane >> 4) << 3), bcol8 = ((lane >> 3) & 1) << 3;
    const uint32_t sb0 = smem_u32(sm);

    for (int c = 0; c < NC; c++) {
        if (c + 1 < NC) {
            int k0n = (c + 1) * 32;
            if (APREP) {
                ua  = *(const uint4*)&Ap[(size_t)(2 * (m0 + prow)) * EMBD + k0n + pc8];
                ual = *(const uint4*)&Ap[(size_t)(2 * (m0 + prow) + 1) * EMBD + k0n + pc8];
            } else {
                #pragma unroll
                for (int i = 0; i < 2; i++) {
                    int seg = tid + i * 512, row = seg >> 3, c4 = (seg & 7) << 2;
                    laf[i] = *(const float4*)&Af[(size_t)(m0 + row) * EMBD + k0n + c4];
                }
            }
            ub  = *(const uint4*)&Bp[(size_t)(2 * (n0 + prow)) * EMBD + k0n + pc8];
            ubl = *(const uint4*)&Bp[(size_t)(2 * (n0 + prow) + 1) * EMBD + k0n + pc8];
        }
        const uint32_t sbase = sb0 + (c & 1) * STAGE_NT;
        #pragma unroll
        for (int ks = 0; ks < 2; ks++) {
            const int k0 = ks * 16;
            uint32_t ah[2][4], al[2][4];
            #pragma unroll
            for (int mt = 0; mt < 2; mt++) {
                int r = wm * 32 + mt * 16 + arow;
                uint32_t ad = sbase + A_HI_O + (r * STR_K + k0 + acol8) * 2;
                ldsm4(ad, ah[mt][0], ah[mt][1], ah[mt][2], ah[mt][3]);
                ldsm4(ad + (A_LO_O - A_HI_O), al[mt][0], al[mt][1], al[mt][2], al[mt][3]);
            }
            uint32_t bh[4][2], bl[4][2];
            #pragma unroll
            for (int bt = 0; bt < 2; bt++) {
                int r = wn * 32 + bt * 16 + brow;
                uint32_t bd = sbase + B_HI_O + (r * STR_K + k0 + bcol8) * 2;
                ldsm4(bd, bh[2 * bt][0], bh[2 * bt][1], bh[2 * bt + 1][0], bh[2 * bt + 1][1]);
                ldsm4(bd + (B_LO_O - B_HI_O),
                      bl[2 * bt][0], bl[2 * bt][1], bl[2 * bt + 1][0], bl[2 * bt + 1][1]);
            }
            #pragma unroll
            for (int mt = 0; mt < 2; mt++)
                #pragma unroll
                for (int nt = 0; nt < 4; nt++) {
                    mma_bf16(acc[mt][nt], ah[mt], bh[nt][0], bh[nt][1]);
                    mma_bf16(acc[mt][nt], ah[mt], bl[nt][0], bl[nt][1]);
                    mma_bf16(acc[mt][nt], al[mt], bh[nt][0], bh[nt][1]);
                }
        }
        if (c + 1 < NC) {
            char* dst = sm + ((c + 1) & 1) * STAGE_NT;
            uint32_t poff = (uint32_t)(prow * STR_K + pc8) * 2;
            if (APREP) {
                *(uint4*)(dst + A_HI_O + poff) = ua;
                *(uint4*)(dst + A_LO_O + poff) = ual;
            } else {
                #pragma unroll
                for (int i = 0; i < 2; i++) {
                    int seg = tid + i * 512, row = seg >> 3, c4 = (seg & 7) << 2;
                    uint2 h, l;
                    cvt_hilo(laf[i], h, l);
                    uint32_t off = (uint32_t)(row * STR_K + c4) * 2;
                    *(uint2*)(dst + A_HI_O + off) = h;
                    *(uint2*)(dst + A_LO_O + off) = l;
                }
            }
            *(uint4*)(dst + B_HI_O + poff) = ub;
            *(uint4*)(dst + B_LO_O + poff) = ubl;
        }
        __syncthreads();
    }

    const int rofs = lane >> 2, cofs = (lane & 3) * 2;
    #pragma unroll
    for (int mt = 0; mt < 2; mt++)
        #pragma unroll
        for (int nt = 0; nt < 4; nt++) {
            int m = m0 + wm * 32 + mt * 16 + rofs;
            int n = n0 + wn * 32 + nt * 8 + cofs;
            *(float2*)&Cb[(size_t)m * EMBD + n] =
                make_float2(acc[mt][nt][0], acc[mt][nt][1]);
            *(float2*)&Cb[(size_t)(m + 8) * EMBD + n] =
                make_float2(acc[mt][nt][2], acc[mt][nt][3]);
        }
}

__global__ void __launch_bounds__(512)
mma_qkv(float* __restrict__ qp, float* __restrict__ kp, float* __restrict__ vp)
{
    extern __shared__ __align__(16) char sm[];
    const int z = blockIdx.z;
    const __nv_bfloat16* Ap = (z == 0) ? g_xp : g_cp;
    const __nv_bfloat16* Bp = (z == 0) ? g_wqp : ((z == 1) ? g_wkp : g_wvp);
    float* Cb = (z == 0) ? qp : ((z == 1) ? kp : vp);
    nt_body<true>(nullptr, Ap, Bp, Cb, sm, blockIdx.y * 128, blockIdx.x * 128);
}

__global__ void __launch_bounds__(512)
mma_out(const float* __restrict__ A, float* __restrict__ C)
{
    extern __shared__ __align__(16) char sm[];
    nt_body<false>(A, nullptr, g_wop, C, sm, blockIdx.y * 128, blockIdx.x * 128);
}

// ===========================================================================
// Fused attention (R8 structure): phase 1 hi-only stats, phase 2 exact
// scores + weights (approx inv) + AV; O normalized by EXACT phase-2 sums.
// ===========================================================================
#define QSTR  72
#define F_LO  18432
#define FQ    0
#define FK0   36864
#define FK1   73728
#define FV0   110592
#define FV1   147456
#define FSMEM 184320

__device__ __forceinline__ void fill64(const float* __restrict__ src, char* dst, int tid) {
    #pragma unroll
    for (int i = 0; i < 8; i++) {
        int seg = tid + i * 256, row = seg >> 4, c4 = (seg & 15) << 2;
        float4 v = *(const float4*)&src[(size_t)row * EMBD + c4];
        uint2 h, l;
        cvt_hilo(v, h, l);
        uint32_t off = (uint32_t)(row * QSTR + c4) * 2;
        *(uint2*)(dst + off) = h;
        *(uint2*)(dst + F_LO + off) = l;
    }
}
__device__ __forceinline__ void fill64_hi(const float* __restrict__ src, char* dst, int tid) {
    #pragma unroll
    for (int i = 0; i < 8; i++) {
        int seg = tid + i * 256, row = seg >> 4, c4 = (seg & 15) << 2;
        float4 v = *(const float4*)&src[(size_t)row * EMBD + c4];
        __nv_bfloat162 h0 = __floats2bfloat162_rn(v.x, v.y);
        __nv_bfloat162 h1 = __floats2bfloat162_rn(v.z, v.w);
        uint32_t off = (uint32_t)(row * QSTR + c4) * 2;
        *(uint2*)(dst + off) = make_uint2(*(uint32_t*)&h0, *(uint32_t*)&h1);
    }
}

#define SCORE_TILE(accv, smK)                                                    \
    do {                                                                          \
        _Pragma("unroll")                                                         \
        for (int ks = 0; ks < 4; ks++) {                                          \
            uint32_t bh[16][2], bl[16][2];                                        \
            _Pragma("unroll")                                                     \
            for (int bp = 0; bp < 8; bp++) {                                      \
                uint32_t bd = (smK) + ((bp * 16 + brow) * QSTR + ks * 16 + bcol8) * 2; \
                ldsm4(bd, bh[2 * bp][0], bh[2 * bp][1], bh[2 * bp + 1][0], bh[2 * bp + 1][1]); \
                ldsm4(bd + F_LO, bl[2 * bp][0], bl[2 * bp][1], bl[2 * bp + 1][0], bl[2 * bp + 1][1]); \
            }                                                                     \
            _Pragma("unroll")                                                     \
            for (int nt = 0; nt < 16; nt++) {                                     \
                mma_bf16(accv[nt], qh[ks], bh[nt][0], bh[nt][1]);                 \
                mma_bf16(accv[nt], qh[ks], bl[nt][0], bl[nt][1]);                 \
                mma_bf16(accv[nt], ql[ks], bh[nt][0], bh[nt][1]);                 \
            }                                                                     \
        }                                                                         \
    } while (0)

#define SCORE_TILE_HI(accv, smK)                                                 \
    do {                                                                          \
        _Pragma("unroll")                                                         \
        for (int ks = 0; ks < 4; ks++) {                                          \
            uint32_t bh[16][2];                                                   \
            _Pragma("unroll")                                                     \
            for (int bp = 0; bp < 8; bp++) {                                      \
                uint32_t bd = (smK) + ((bp * 16 + brow) * QSTR + ks * 16 + bcol8) * 2; \
                ldsm4(bd, bh[2 * bp][0], bh[2 * bp][1], bh[2 * bp + 1][0], bh[2 * bp + 1][1]); \
            }                                                                     \
            _Pragma("unroll")                                                     \
            for (int nt = 0; nt < 16; nt++)                                       \
                mma_bf16(accv[nt], qh[ks], bh[nt][0], bh[nt][1]);                 \
        }                                                                         \
    } while (0)

__global__ void __launch_bounds__(256)
fused_attn(const float* __restrict__ Q, const float* __restrict__ K,
           const float* __restrict__ V, const int* __restrict__ mask,
           float* __restrict__ Wt, float* __restrict__ O, int write_w)
{
    extern __shared__ __align__(16) char sm[];
    const uint32_t sb = smem_u32(sm);
    const int tid = threadIdx.x, lane = tid & 31, w = tid >> 5;
    const int z = blockIdx.y, b = z >> 4, h = z & 15;
    const int m0 = blockIdx.x * 128;

    const float* Qb = Q + (size_t)b * Tt * EMBD + h * HEAD;
    const float* Kb = K + (size_t)b * Tt * EMBD + h * HEAD;
    const float* Vb = V + (size_t)b * Tt * EMBD + h * HEAD;
    const int* mb = mask + (size_t)b * Tt * Tt + (size_t)m0 * Tt;

    const int g = lane >> 2, i2 = (lane & 3) << 1;
    const int arow = lane & 15, acol8 = (lane >> 4) << 3;
    const int brow = (lane & 7) + ((lane >> 4) << 3), bcol8 = ((lane >> 3) & 1) << 3;
    const int tbrow = (lane & 7) + (((lane >> 3) & 1) << 3), tbcol8 = (lane >> 4) << 3;

    fill64(Qb + (size_t)m0 * EMBD, sm + FQ, tid);
    fill64_hi(Kb, sm + FK0, tid);
    __syncthreads();

    uint32_t qh[4][4], ql[4][4];
    #pragma unroll
    for (int ks = 0; ks < 4; ks++) {
        uint32_t ad = sb + FQ + ((w * 16 + arow) * QSTR + ks * 16 + acol8) * 2;
        ldsm4(ad, qh[ks][0], qh[ks][1], qh[ks][2], qh[ks][3]);
        ldsm4(ad + F_LO, ql[ks][0], ql[ks][1], ql[ks][2], ql[ks][3]);
    }

    const int trow = w * 16 + g;

    // ---------------- phase 1: stats (hi-only scores) ----------------
    float rm0 = -3.0e38f, rm1 = -3.0e38f, rs0 = 0.f, rs1 = 0.f;
    for (int st = 0; st < 8; st++) {
        if (st < 7) fill64_hi(Kb + (size_t)(st + 1) * 128 * EMBD,
                              sm + (((st + 1) & 1) ? FK1 : FK0), tid);
        float acc[16][4] = {};
        const uint32_t smK = sb + ((st & 1) ? FK1 : FK0);
        SCORE_TILE_HI(acc, smK);

        const int* mr0 = mb + (size_t)trow * Tt + st * 128;
        const int* mr1 = mr0 + 8 * Tt;
        #pragma unroll
        for (int nt = 0; nt < 16; nt++) {
            int2 k0 = *(const int2*)&mr0[nt * 8 + i2];
            int2 k1 = *(const int2*)&mr1[nt * 8 + i2];
            acc[nt][0] = k0.x ? NEG_BIG : acc[nt][0] * 0.125f;
            acc[nt][1] = k0.y ? NEG_BIG : acc[nt][1] * 0.125f;
            acc[nt][2] = k1.x ? NEG_BIG : acc[nt][2] * 0.125f;
            acc[nt][3] = k1.y ? NEG_BIG : acc[nt][3] * 0.125f;
        }
        float t0 = -3.0e38f, t1 = -3.0e38f;
        #pragma unroll
        for (int nt = 0; nt < 16; nt++) {
            t0 = fmaxf(t0, fmaxf(acc[nt][0], acc[nt][1]));
            t1 = fmaxf(t1, fmaxf(acc[nt][2], acc[nt][3]));
        }
        t0 = fmaxf(t0, __shfl_xor_sync(0xffffffffu, t0, 1));
        t0 = fmaxf(t0, __shfl_xor_sync(0xffffffffu, t0, 2));
        t1 = fmaxf(t1, __shfl_xor_sync(0xffffffffu, t1, 1));
        t1 = fmaxf(t1, __shfl_xor_sync(0xffffffffu, t1, 2));
        float nm0 = fmaxf(rm0, t0), nm1 = fmaxf(rm1, t1);
        float s0 = 0.f, s1 = 0.f;
        #pragma unroll
        for (int nt = 0; nt < 16; nt++) {
            s0 += __expf(acc[nt][0] - nm0) + __expf(acc[nt][1] - nm0);
            s1 += __expf(acc[nt][2] - nm1) + __expf(acc[nt][3] - nm1);
        }
        s0 += __shfl_xor_sync(0xffffffffu, s0, 1);
        s0 += __shfl_xor_sync(0xffffffffu, s0, 2);
        s1 += __shfl_xor_sync(0xffffffffu, s1, 1);
        s1 += __shfl_xor_sync(0xffffffffu, s1, 2);
        rs0 = rs0 * __expf(rm0 - nm0) + s0;  rm0 = nm0;
        rs1 = rs1 * __expf(rm1 - nm1) + s1;  rm1 = nm1;
        __syncthreads();
    }
    const float inv0 = (rm0 <= -1e29f) ? 0.f : 1.f / rs0;
    const float inv1 = (rm1 <= -1e29f) ? 0.f : 1.f / rs1;

    // ---------------- phase 2: exact scores, weights + AV + exact sums ------
    fill64(Kb, sm + FK0, tid);
    fill64(Vb, sm + FV0, tid);
    __syncthreads();

    float acco[8][4] = {};
    float se0 = 0.f, se1 = 0.f;   // exact sums of exp(s_exact - rm)
    float* wrow0 = Wt + (size_t)z * Tt * Tt + (size_t)(m0 + trow) * Tt;
    float* wrow1 = wrow0 + 8 * Tt;

    for (int st = 0; st < 8; st++) {
        if (st < 7) {
            const int nb = (st + 1) & 1;
            fill64(Kb + (size_t)(st + 1) * 128 * EMBD, sm + (nb ? FK1 : FK0), tid);
            fill64(Vb + (size_t)(st + 1) * 128 * EMBD, sm + (nb ? FV1 : FV0), tid);
        }
        float acc[16][4] = {};
        const uint32_t smK = sb + ((st & 1) ? FK1 : FK0);
        const uint32_t smV = sb + ((st & 1) ? FV1 : FV0);
        SCORE_TILE(acc, smK);

        const int* mr0 = mb + (size_t)trow * Tt + st * 128;
        const int* mr1 = mr0 + 8 * Tt;
        float s0 = 0.f, s1 = 0.f;
        #pragma unroll
        for (int nt = 0; nt < 16; nt++) {
            int2 k0 = *(const int2*)&mr0[nt * 8 + i2];
            int2 k1 = *(const int2*)&mr1[nt * 8 + i2];
            float e0 = k0.x ? 0.f : __expf(acc[nt][0] * 0.125f - rm0);
            float e1 = k0.y ? 0.f : __expf(acc[nt][1] * 0.125f - rm0);
            float e2 = k1.x ? 0.f : __expf(acc[nt][2] * 0.125f - rm1);
            float e3 = k1.y ? 0.f : __expf(acc[nt][3] * 0.125f - rm1);
            s0 += e0 + e1;
            s1 += e2 + e3;
            acc[nt][0] = e0 * inv0;
            acc[nt][1] = e1 * inv0;
            acc[nt][2] = e2 * inv1;
            acc[nt][3] = e3 * inv1;
        }
        s0 += __shfl_xor_sync(0xffffffffu, s0, 1);
        s0 += __shfl_xor_sync(0xffffffffu, s0, 2);
        s1 += __shfl_xor_sync(0xffffffffu, s1, 1);
        s1 += __shfl_xor_sync(0xffffffffu, s1, 2);
        se0 += s0;
        se1 += s1;

        if (write_w) {
            #pragma unroll
            for (int nt = 0; nt < 16; nt++) {
                *(float2*)&wrow0[st * 128 + nt * 8 + i2] = make_float2(acc[nt][0], acc[nt][1]);
                *(float2*)&wrow1[st * 128 + nt * 8 + i2] = make_float2(acc[nt][2], acc[nt][3]);
            }
        }
        #pragma unroll
        for (int j = 0; j < 8; j++) {
            uint32_t ph[4], pl[4];
            pack2(acc[2 * j][0],     acc[2 * j][1],     ph[0], pl[0]);
            pack2(acc[2 * j][2],     acc[2 * j][3],     ph[1], pl[1]);
            pack2(acc[2 * j + 1][0], acc[2 * j + 1][1], ph[2], pl[2]);
            pack2(acc[2 * j + 1][2], acc[2 * j + 1][3], ph[3], pl[3]);
            uint32_t vh[8][2], vl[8][2];
            #pragma unroll
            for (int bt = 0; bt < 4; bt++) {
                uint32_t vd = smV + ((j * 16 + tbrow) * QSTR + bt * 16 + tbcol8) * 2;
                ldsm4t(vd, vh[2 * bt][0], vh[2 * bt][1], vh[2 * bt + 1][0], vh[2 * bt + 1][1]);
                ldsm4t(vd + F_LO, vl[2 * bt][0], vl[2 * bt][1], vl[2 * bt + 1][0], vl[2 * bt + 1][1]);
            }
            #pragma unroll
            for (int ntv = 0; ntv < 8; ntv++) {
                mma_bf16(acco[ntv], ph, vh[ntv][0], vh[ntv][1]);
                mma_bf16(acco[ntv], ph, vl[ntv][0], vl[ntv][1]);
                mma_bf16(acco[ntv], pl, vh[ntv][0], vh[ntv][1]);
            }
        }
        __syncthreads();
    }

    // O correction: acco used P = e*inv0; exact O = acco / (inv0 * se_exact)
    const float fac0 = (inv0 > 0.f && se0 > 0.f) ? 1.f / (inv0 * se0) : 0.f;
    const float fac1 = (inv1 > 0.f && se1 > 0.f) ? 1.f / (inv1 * se1) : 0.f;

    float* Ob = O + (size_t)b * Tt * EMBD + h * HEAD + (size_t)(m0 + trow) * EMBD;
    #pragma unroll
    for (int ntv = 0; ntv < 8; ntv++) {
        *(float2*)&Ob[ntv * 8 + i2] =
            make_float2(acco[ntv][0] * fac0, acco[ntv][1] * fac0);
        *(float2*)&Ob[8 * EMBD + ntv * 8 + i2] =
            make_float2(acco[ntv][2] * fac1, acco[ntv][3] * fac1);
    }
}

// ===========================================================================
extern "C" void kernel_launch(void* const* d_in, const int* in_sizes, int n_in,
                              void* d_out, int out_size)
{
    const float* x    = (const float*)d_in[0];
    const float* ctx  = (const float*)d_in[1];
    const int*   mask = (const int*)d_in[2];
    const float* WQ = (const float*)d_in[3];
    const float* WK = (const float*)d_in[4];
    const float* WV = (const float*)d_in[5];
    const float* WO = (const float*)d_in[6];
    float* out = (float*)d_out;

    float *qp, *kp, *vp, *op;
    cudaGetSymbolAddress((void**)&qp, g_Q);
    cudaGetSymbolAddress((void**)&kp, g_K);
    cudaGetSymbolAddress((void**)&vp, g_V);
    cudaGetSymbolAddress((void**)&op, g_O);

    const size_t merged_elems = (size_t)BTR * EMBD;
    const size_t weight_elems = (size_t)Bb * Hh * Tt * Tt;
    const int write_w = ((size_t)out_size >= merged_elems + weight_elems) ? 1 : 0;
    float* wt;
    if (write_w) {
        wt = out + merged_elems;
    } else {
        cudaGetSymbolAddress((void**)&wt, g_W);
    }

    const int SMEM_NT = 2 * STAGE_NT;   // 80 KB
    cudaFuncSetAttribute(mma_qkv, cudaFuncAttributeMaxDynamicSharedMemorySize, SMEM_NT);
    cudaFuncSetAttribute(mma_out, cudaFuncAttributeMaxDynamicSharedMemorySize, SMEM_NT);
    cudaFuncSetAttribute(fused_attn, cudaFuncAttributeMaxDynamicSharedMemorySize, FSMEM);

    // prep all operand matrices to interleaved bf16 hi/lo
    dim3 gp(4096, 1, 6);
    prep_all<<<gp, 256>>>(x, ctx, WQ, WK, WV, WO);

    // Q/K/V projections (prepped operands, zero in-loop conversion)
    dim3 gqkv(EMBD / 128, BTR / 128, 3);
    mma_qkv<<<gqkv, 512, SMEM_NT>>>(qp, kp, vp);

    // fused attention (R8 two-phase + exact-O correction)
    dim3 gf(Tt / 128, Bb * Hh);
    fused_attn<<<gf, 256, FSMEM>>>(qp, kp, vp, mask, wt, op, write_w);

    // output projection (A fp32, B prepped)
    dim3 gout(EMBD / 128, BTR / 128);
    mma_out<<<gout, 512, SMEM_NT>>>(op, out);
}

// round 13
// speedup vs baseline: 1.0425x; 1.0425x over previous
#include <cuda_runtime.h>
#include <cuda_bf16.h>
#include <cstdint>

#define Bb   4
#define Tt   1024
#define EMBD 1024
#define Hh   16
#define HEAD 64
#define BTR  (Bb * Tt)
#define NEG_BIG (-1e30f)

static __device__ float g_Q[(size_t)BTR * EMBD];
static __device__ float g_K[(size_t)BTR * EMBD];
static __device__ float g_V[(size_t)BTR * EMBD];
static __device__ float g_O[(size_t)BTR * EMBD];
static __device__ float g_W[(size_t)Bb * Hh * Tt * Tt];

// chunk-blocked bf16 hi/lo: for chunk c (32 k-cols), row r:
//   128B line at ((c*R + r) * 64) bf16: [0,32)=hi, [32,64)=lo
static __device__ __align__(16) __nv_bfloat16 g_xp[2ull * BTR * EMBD];
static __device__ __align__(16) __nv_bfloat16 g_cp[2ull * BTR * EMBD];
static __device__ __align__(16) __nv_bfloat16 g_wqp[2ull * EMBD * EMBD];
static __device__ __align__(16) __nv_bfloat16 g_wkp[2ull * EMBD * EMBD];
static __device__ __align__(16) __nv_bfloat16 g_wvp[2ull * EMBD * EMBD];
static __device__ __align__(16) __nv_bfloat16 g_wop[2ull * EMBD * EMBD];

// ===========================================================================
// helpers
// ===========================================================================
__device__ __forceinline__ uint32_t smem_u32(const void* p) {
    uint32_t a;
    asm("{ .reg .u64 t; cvta.to.shared.u64 t, %1; cvt.u32.u64 %0, t; }" : "=r"(a) : "l"(p));
    return a;
}
__device__ __forceinline__ void ldsm4(uint32_t addr, uint32_t& r0, uint32_t& r1,
                                      uint32_t& r2, uint32_t& r3) {
    asm volatile("ldmatrix.sync.aligned.m8n8.x4.shared.b16 {%0,%1,%2,%3}, [%4];"
                 : "=r"(r0), "=r"(r1), "=r"(r2), "=r"(r3) : "r"(addr));
}
__device__ __forceinline__ void ldsm4t(uint32_t addr, uint32_t& r0, uint32_t& r1,
                                       uint32_t& r2, uint32_t& r3) {
    asm volatile("ldmatrix.sync.aligned.m8n8.x4.trans.shared.b16 {%0,%1,%2,%3}, [%4];"
                 : "=r"(r0), "=r"(r1), "=r"(r2), "=r"(r3) : "r"(addr));
}
__device__ __forceinline__ void mma_bf16(float (&d)[4], const uint32_t (&a)[4],
                                         uint32_t b0, uint32_t b1) {
    asm volatile("mma.sync.aligned.m16n8k16.row.col.f32.bf16.bf16.f32 "
                 "{%0,%1,%2,%3},{%4,%5,%6,%7},{%8,%9},{%0,%1,%2,%3};"
                 : "+f"(d[0]), "+f"(d[1]), "+f"(d[2]), "+f"(d[3])
                 : "r"(a[0]), "r"(a[1]), "r"(a[2]), "r"(a[3]), "r"(b0), "r"(b1));
}
__device__ __forceinline__ void cvt_hilo(float4 v, uint2& hi, uint2& lo) {
    __nv_bfloat162 h0 = __floats2bfloat162_rn(v.x, v.y);
    __nv_bfloat162 h1 = __floats2bfloat162_rn(v.z, v.w);
    float rx = v.x - __bfloat162float(h0.x);
    float ry = v.y - __bfloat162float(h0.y);
    float rz = v.z - __bfloat162float(h1.x);
    float rw = v.w - __bfloat162float(h1.y);
    __nv_bfloat162 l0 = __floats2bfloat162_rn(rx, ry);
    __nv_bfloat162 l1 = __floats2bfloat162_rn(rz, rw);
    hi = make_uint2(*(uint32_t*)&h0, *(uint32_t*)&h1);
    lo = make_uint2(*(uint32_t*)&l0, *(uint32_t*)&l1);
}
__device__ __forceinline__ void pack2(float x, float y, uint32_t& h, uint32_t& l) {
    __nv_bfloat162 hh = __floats2bfloat162_rn(x, y);
    float rx = x - __bfloat162float(hh.x);
    float ry = y - __bfloat162float(hh.y);
    __nv_bfloat162 ll = __floats2bfloat162_rn(rx, ry);
    h = *(uint32_t*)&hh;
    l = *(uint32_t*)&ll;
}

// ===========================================================================
// prep: fp32 -> chunk-blocked bf16 hi/lo (full 128B lines per (chunk,row))
// ===========================================================================
__global__ void __launch_bounds__(256)
prep_all(const float* __restrict__ x, const float* __restrict__ ctx,
         const float* __restrict__ wq, const float* __restrict__ wk,
         const float* __restrict__ wv, const float* __restrict__ wo)
{
    const int z = blockIdx.z;
    const float* srcs[6] = {x, ctx, wq, wk, wv, wo};
    __nv_bfloat16* dsts[6] = {g_xp, g_cp, g_wqp, g_wkp, g_wvp, g_wop};
    const int lgR = (z < 2) ? 12 : 10;          // R = 4096 or 1024
    const int R = 1 << lgR;

    size_t t = (size_t)blockIdx.x * 256 + threadIdx.x;
    if (t >= (size_t)R * 128) return;           // R*1024/8 groups of 8 elems
    const int j8 = (int)(t & 3);                // 8-elem group within chunk
    const size_t rc = t >> 2;
    const int r = (int)(rc & (R - 1));
    const int c = (int)(rc >> lgR);

    const float4* s = (const float4*)srcs[z];
    size_t sidx = (size_t)r * 256 + c * 8 + j8 * 2;
    uint2 h0, l0, h1, l1;
    cvt_hilo(s[sidx], h0, l0);
    cvt_hilo(s[sidx + 1], h1, l1);

    __nv_bfloat16* d = dsts[z];
    size_t base = ((size_t)c * R + r) * 64;
    *(uint4*)&d[base + j8 * 8]      = make_uint4(h0.x, h0.y, h1.x, h1.y);
    *(uint4*)&d[base + 32 + j8 * 8] = make_uint4(l0.x, l0.y, l1.x, l1.y);
}

// ===========================================================================
// NT GEMM (C = A * B^T), 128x128 block, BK=32, 512 threads / 16 warps,
// bf16 hi/lo 3-pass. B always chunk-blocked prepped. APREP: A prepped/fp32.
// ===========================================================================
#define STR_K  40
#define A_HI_O 0
#define A_LO_O 10240
#define B_HI_O 20480
#define B_LO_O 30720
#define STAGE_NT 40960

template <bool APREP>
__device__ __forceinline__ void nt_body(const float* __restrict__ Af,
                                        const __nv_bfloat16* __restrict__ Ap, int RA,
                                        const __nv_bfloat16* __restrict__ Bp, int RB,
                                        float* __restrict__ Cb, char* sm,
                                        int m0, int n0)
{
    const int tid = threadIdx.x, lane = tid & 31, wid = tid >> 5;
    const int NC = EMBD / 32;

    float acc[2][4][4] = {};
    float4 laf[2];
    uint4 ua, ual, ub, ubl;

    const int prow = tid >> 2, pc8 = (tid & 3) << 3;

    // prologue loads (chunk 0)
    if (APREP) {
        size_t ab = ((size_t)0 * RA + m0 + prow) * 64;
        ua  = *(const uint4*)&Ap[ab + pc8];
        ual = *(const uint4*)&Ap[ab + 32 + pc8];
    } else {
        #pragma unroll
        for (int i = 0; i < 2; i++) {
            int seg = tid + i * 512, row = seg >> 3, c4 = (seg & 7) << 2;
            laf[i] = *(const float4*)&Af[(size_t)(m0 + row) * EMBD + c4];
        }
    }
    {
        size_t bb = ((size_t)0 * RB + n0 + prow) * 64;
        ub  = *(const uint4*)&Bp[bb + pc8];
        ubl = *(const uint4*)&Bp[bb + 32 + pc8];
    }
    // prologue stores
    {
        uint32_t poff = (uint32_t)(prow * STR_K + pc8) * 2;
        if (APREP) {
            *(uint4*)(sm + A_HI_O + poff) = ua;
            *(uint4*)(sm + A_LO_O + poff) = ual;
        } else {
            #pragma unroll
            for (int i = 0; i < 2; i++) {
                int seg = tid + i * 512, row = seg >> 3, c4 = (seg & 7) << 2;
                uint2 h, l;
                cvt_hilo(laf[i], h, l);
                uint32_t off = (uint32_t)(row * STR_K + c4) * 2;
                *(uint2*)(sm + A_HI_O + off) = h;
                *(uint2*)(sm + A_LO_O + off) = l;
            }
        }
        *(uint4*)(sm + B_HI_O + poff) = ub;
        *(uint4*)(sm + B_LO_O + poff) = ubl;
    }
    __syncthreads();

    const int wm = wid >> 2, wn = wid & 3;
    const int arow = lane & 15, acol8 = (lane >> 4) << 3;
    const int brow = (lane & 7) + ((lane >> 4) << 3), bcol8 = ((lane >> 3) & 1) << 3;
    const uint32_t sb0 = smem_u32(sm);

    for (int c = 0; c < NC; c++) {
        if (c + 1 < NC) {
            if (APREP) {
                size_t ab = ((size_t)(c + 1) * RA + m0 + prow) * 64;
                ua  = *(const uint4*)&Ap[ab + pc8];
                ual = *(const uint4*)&Ap[ab + 32 + pc8];
            } else {
                int k0n = (c + 1) * 32;
                #pragma unroll
                for (int i = 0; i < 2; i++) {
                    int seg = tid + i * 512, row = seg >> 3, c4 = (seg & 7) << 2;
                    laf[i] = *(const float4*)&Af[(size_t)(m0 + row) * EMBD + k0n + c4];
                }
            }
            size_t bb = ((size_t)(c + 1) * RB + n0 + prow) * 64;
            ub  = *(const uint4*)&Bp[bb + pc8];
            ubl = *(const uint4*)&Bp[bb + 32 + pc8];
        }
        const uint32_t sbase = sb0 + (c & 1) * STAGE_NT;
        #pragma unroll
        for (int ks = 0; ks < 2; ks++) {
            const int k0 = ks * 16;
            uint32_t ah[2][4], al[2][4];
            #pragma unroll
            for (int mt = 0; mt < 2; mt++) {
                int r = wm * 32 + mt * 16 + arow;
                uint32_t ad = sbase + A_HI_O + (r * STR_K + k0 + acol8) * 2;
                ldsm4(ad, ah[mt][0], ah[mt][1], ah[mt][2], ah[mt][3]);
                ldsm4(ad + (A_LO_O - A_HI_O), al[mt][0], al[mt][1], al[mt][2], al[mt][3]);
            }
            uint32_t bh[4][2], bl[4][2];
            #pragma unroll
            for (int bt = 0; bt < 2; bt++) {
                int r = wn * 32 + bt * 16 + brow;
                uint32_t bd = sbase + B_HI_O + (r * STR_K + k0 + bcol8) * 2;
                ldsm4(bd, bh[2 * bt][0], bh[2 * bt][1], bh[2 * bt + 1][0], bh[2 * bt + 1][1]);
                ldsm4(bd + (B_LO_O - B_HI_O),
                      bl[2 * bt][0], bl[2 * bt][1], bl[2 * bt + 1][0], bl[2 * bt + 1][1]);
            }
            #pragma unroll
            for (int mt = 0; mt < 2; mt++)
                #pragma unroll
                for (int nt = 0; nt < 4; nt++) {
                    mma_bf16(acc[mt][nt], ah[mt], bh[nt][0], bh[nt][1]);
                    mma_bf16(acc[mt][nt], ah[mt], bl[nt][0], bl[nt][1]);
                    mma_bf16(acc[mt][nt], al[mt], bh[nt][0], bh[nt][1]);
                }
        }
        if (c + 1 < NC) {
            char* dst = sm + ((c + 1) & 1) * STAGE_NT;
            uint32_t poff = (uint32_t)(prow * STR_K + pc8) * 2;
            if (APREP) {
                *(uint4*)(dst + A_HI_O + poff) = ua;
                *(uint4*)(dst + A_LO_O + poff) = ual;
            } else {
                #pragma unroll
                for (int i = 0; i < 2; i++) {
                    int seg = tid + i * 512, row = seg >> 3, c4 = (seg & 7) << 2;
                    uint2 h, l;
                    cvt_hilo(laf[i], h, l);
                    uint32_t off = (uint32_t)(row * STR_K + c4) * 2;
                    *(uint2*)(dst + A_HI_O + off) = h;
                    *(uint2*)(dst + A_LO_O + off) = l;
                }
            }
            *(uint4*)(dst + B_HI_O + poff) = ub;
            *(uint4*)(dst + B_LO_O + poff) = ubl;
        }
        __syncthreads();
    }

    const int rofs = lane >> 2, cofs = (lane & 3) * 2;
    #pragma unroll
    for (int mt = 0; mt < 2; mt++)
        #pragma unroll
        for (int nt = 0; nt < 4; nt++) {
            int m = m0 + wm * 32 + mt * 16 + rofs;
            int n = n0 + wn * 32 + nt * 8 + cofs;
            *(float2*)&Cb[(size_t)m * EMBD + n] =
                make_float2(acc[mt][nt][0], acc[mt][nt][1]);
            *(float2*)&Cb[(size_t)(m + 8) * EMBD + n] =
                make_float2(acc[mt][nt][2], acc[mt][nt][3]);
        }
}

__global__ void __launch_bounds__(512)
mma_qkv(float* __restrict__ qp, float* __restrict__ kp, float* __restrict__ vp)
{
    extern __shared__ __align__(16) char sm[];
    const int z = blockIdx.z;
    const __nv_bfloat16* Ap = (z == 0) ? g_xp : g_cp;
    const __nv_bfloat16* Bp = (z == 0) ? g_wqp : ((z == 1) ? g_wkp : g_wvp);
    float* Cb = (z == 0) ? qp : ((z == 1) ? kp : vp);
    nt_body<true>(nullptr, Ap, BTR, Bp, EMBD, Cb, sm, blockIdx.y * 128, blockIdx.x * 128);
}

__global__ void __launch_bounds__(512)
mma_out(const float* __restrict__ A, float* __restrict__ C)
{
    extern __shared__ __align__(16) char sm[];
    nt_body<false>(A, nullptr, 0, g_wop, EMBD, C, sm, blockIdx.y * 128, blockIdx.x * 128);
}

// ===========================================================================
// Fused attention (R8 structure): phase 1 hi-only stats, phase 2 exact
// scores + weights (approx inv) + AV; O rescaled by exact phase-2 sums.
// ===========================================================================
#define QSTR  72
#define F_LO  18432
#define FQ    0
#define FK0   36864
#define FK1   73728
#define FV0   110592
#define FV1   147456
#define FSMEM 184320

__device__ __forceinline__ void fill64(const float* __restrict__ src, char* dst, int tid) {
    #pragma unroll
    for (int i = 0; i < 8; i++) {
        int seg = tid + i * 256, row = seg >> 4, c4 = (seg & 15) << 2;
        float4 v = *(const float4*)&src[(size_t)row * EMBD + c4];
        uint2 h, l;
        cvt_hilo(v, h, l);
        uint32_t off = (uint32_t)(row * QSTR + c4) * 2;
        *(uint2*)(dst + off) = h;
        *(uint2*)(dst + F_LO + off) = l;
    }
}
__device__ __forceinline__ void fill64_hi(const float* __restrict__ src, char* dst, int tid) {
    #pragma unroll
    for (int i = 0; i < 8; i++) {
        int seg = tid + i * 256, row = seg >> 4, c4 = (seg & 15) << 2;
        float4 v = *(const float4*)&src[(size_t)row * EMBD + c4];
        __nv_bfloat162 h0 = __floats2bfloat162_rn(v.x, v.y);
        __nv_bfloat162 h1 = __floats2bfloat162_rn(v.z, v.w);
        uint32_t off = (uint32_t)(row * QSTR + c4) * 2;
        *(uint2*)(dst + off) = make_uint2(*(uint32_t*)&h0, *(uint32_t*)&h1);
    }
}

#define SCORE_TILE(accv, smK)                                                    \
    do {                                                                          \
        _Pragma("unroll")                                                         \
        for (int ks = 0; ks < 4; ks++) {                                          \
            uint32_t bh[16][2], bl[16][2];                                        \
            _Pragma("unroll")                                                     \
            for (int bp = 0; bp < 8; bp++) {                                      \
                uint32_t bd = (smK) + ((bp * 16 + brow) * QSTR + ks * 16 + bcol8) * 2; \
                ldsm4(bd, bh[2 * bp][0], bh[2 * bp][1], bh[2 * bp + 1][0], bh[2 * bp + 1][1]); \
                ldsm4(bd + F_LO, bl[2 * bp][0], bl[2 * bp][1], bl[2 * bp + 1][0], bl[2 * bp + 1][1]); \
            }                                                                     \
            _Pragma("unroll")                                                     \
            for (int nt = 0; nt < 16; nt++) {                                     \
                mma_bf16(accv[nt], qh[ks], bh[nt][0], bh[nt][1]);                 \
                mma_bf16(accv[nt], qh[ks], bl[nt][0], bl[nt][1]);                 \
                mma_bf16(accv[nt], ql[ks], bh[nt][0], bh[nt][1]);                 \
            }                                                                     \
        }                                                                         \
    } while (0)

#define SCORE_TILE_HI(accv, smK)                                                 \
    do {                                                                          \
        _Pragma("unroll")                                                         \
        for (int ks = 0; ks < 4; ks++) {                                          \
            uint32_t bh[16][2];                                                   \
            _Pragma("unroll")                                                     \
            for (int bp = 0; bp < 8; bp++) {                                      \
                uint32_t bd = (smK) + ((bp * 16 + brow) * QSTR + ks * 16 + bcol8) * 2; \
                ldsm4(bd, bh[2 * bp][0], bh[2 * bp][1], bh[2 * bp + 1][0], bh[2 * bp + 1][1]); \
            }                                                                     \
            _Pragma("unroll")                                                     \
            for (int nt = 0; nt < 16; nt++)                                       \
                mma_bf16(accv[nt], qh[ks], bh[nt][0], bh[nt][1]);                 \
        }                                                                         \
    } while (0)

__global__ void __launch_bounds__(256)
fused_attn(const float* __restrict__ Q, const float* __restrict__ K,
           const float* __restrict__ V, const int* __restrict__ mask,
           float* __restrict__ Wt, float* __restrict__ O, int write_w)
{
    extern __shared__ __align__(16) char sm[];
    const uint32_t sb = smem_u32(sm);
    const int tid = threadIdx.x, lane = tid & 31, w = tid >> 5;
    const int z = blockIdx.y, b = z >> 4, h = z & 15;
    const int m0 = blockIdx.x * 128;

    const float* Qb = Q + (size_t)b * Tt * EMBD + h * HEAD;
    const float* Kb = K + (size_t)b * Tt * EMBD + h * HEAD;
    const float* Vb = V + (size_t)b * Tt * EMBD + h * HEAD;
    const int* mb = mask + (size_t)b * Tt * Tt + (size_t)m0 * Tt;

    const int g = lane >> 2, i2 = (lane & 3) << 1;
    const int arow = lane & 15, acol8 = (lane >> 4) << 3;
    const int brow = (lane & 7) + ((lane >> 4) << 3), bcol8 = ((lane >> 3) & 1) << 3;
    const int tbrow = (lane & 7) + (((lane >> 3) & 1) << 3), tbcol8 = (lane >> 4) << 3;

    fill64(Qb + (size_t)m0 * EMBD, sm + FQ, tid);
    fill64_hi(Kb, sm + FK0, tid);
    __syncthreads();

    uint32_t qh[4][4], ql[4][4];
    #pragma unroll
    for (int ks = 0; ks < 4; ks++) {
        uint32_t ad = sb + FQ + ((w * 16 + arow) * QSTR + ks * 16 + acol8) * 2;
        ldsm4(ad, qh[ks][0], qh[ks][1], qh[ks][2], qh[ks][3]);
        ldsm4(ad + F_LO, ql[ks][0], ql[ks][1], ql[ks][2], ql[ks][3]);
    }

    const int trow = w * 16 + g;

    // ---------------- phase 1: stats (hi-only scores) ----------------
    float rm0 = -3.0e38f, rm1 = -3.0e38f, rs0 = 0.f, rs1 = 0.f;
    for (int st = 0; st < 8; st++) {
        if (st < 7) fill64_hi(Kb + (size_t)(st + 1) * 128 * EMBD,
                              sm + (((st + 1) & 1) ? FK1 : FK0), tid);
        float acc[16][4] = {};
        const uint32_t smK = sb + ((st & 1) ? FK1 : FK0);
        SCORE_TILE_HI(acc, smK);

        const int* mr0 = mb + (size_t)trow * Tt + st * 128;
        const int* mr1 = mr0 + 8 * Tt;
        #pragma unroll
        for (int nt = 0; nt < 16; nt++) {
            int2 k0 = *(const int2*)&mr0[nt * 8 + i2];
            int2 k1 = *(const int2*)&mr1[nt * 8 + i2];
            acc[nt][0] = k0.x ? NEG_BIG : acc[nt][0] * 0.125f;
            acc[nt][1] = k0.y ? NEG_BIG : acc[nt][1] * 0.125f;
            acc[nt][2] = k1.x ? NEG_BIG : acc[nt][2] * 0.125f;
            acc[nt][3] = k1.y ? NEG_BIG : acc[nt][3] * 0.125f;
        }
        float t0 = -3.0e38f, t1 = -3.0e38f;
        #pragma unroll
        for (int nt = 0; nt < 16; nt++) {
            t0 = fmaxf(t0, fmaxf(acc[nt][0], acc[nt][1]));
            t1 = fmaxf(t1, fmaxf(acc[nt][2], acc[nt][3]));
        }
        t0 = fmaxf(t0, __shfl_xor_sync(0xffffffffu, t0, 1));
        t0 = fmaxf(t0, __shfl_xor_sync(0xffffffffu, t0, 2));
        t1 = fmaxf(t1, __shfl_xor_sync(0xffffffffu, t1, 1));
        t1 = fmaxf(t1, __shfl_xor_sync(0xffffffffu, t1, 2));
        float nm0 = fmaxf(rm0, t0), nm1 = fmaxf(rm1, t1);
        float s0 = 0.f, s1 = 0.f;
        #pragma unroll
        for (int nt = 0; nt < 16; nt++) {
            s0 += __expf(acc[nt][0] - nm0) + __expf(acc[nt][1] - nm0);
            s1 += __expf(acc[nt][2] - nm1) + __expf(acc[nt][3] - nm1);
        }
        s0 += __shfl_xor_sync(0xffffffffu, s0, 1);
        s0 += __shfl_xor_sync(0xffffffffu, s0, 2);
        s1 += __shfl_xor_sync(0xffffffffu, s1, 1);
        s1 += __shfl_xor_sync(0xffffffffu, s1, 2);
        rs0 = rs0 * __expf(rm0 - nm0) + s0;  rm0 = nm0;
        rs1 = rs1 * __expf(rm1 - nm1) + s1;  rm1 = nm1;
        __syncthreads();
    }
    const float inv0 = (rm0 <= -1e29f) ? 0.f : 1.f / rs0;
    const float inv1 = (rm1 <= -1e29f) ? 0.f : 1.f / rs1;

    // ---------------- phase 2: exact scores, weights + AV + exact sums ------
    fill64(Kb, sm + FK0, tid);
    fill64(Vb, sm + FV0, tid);
    __syncthreads();

    float acco[8][4] = {};
    float se0 = 0.f, se1 = 0.f;
    float* wrow0 = Wt + (size_t)z * Tt * Tt + (size_t)(m0 + trow) * Tt;
    float* wrow1 = wrow0 + 8 * Tt;

    for (int st = 0; st < 8; st++) {
        if (st < 7) {
            const int nb = (st + 1) & 1;
            fill64(Kb + (size_t)(st + 1) * 128 * EMBD, sm + (nb ? FK1 : FK0), tid);
            fill64(Vb + (size_t)(st + 1) * 128 * EMBD, sm + (nb ? FV1 : FV0), tid);
        }
        float acc[16][4] = {};
        const uint32_t smK = sb + ((st & 1) ? FK1 : FK0);
        const uint32_t smV = sb + ((st & 1) ? FV1 : FV0);
        SCORE_TILE(acc, smK);

        const int* mr0 = mb + (size_t)trow * Tt + st * 128;
        const int* mr1 = mr0 + 8 * Tt;
        float s0 = 0.f, s1 = 0.f;
        #pragma unroll
        for (int nt = 0; nt < 16; nt++) {
            int2 k0 = *(const int2*)&mr0[nt * 8 + i2];
            int2 k1 = *(const int2*)&mr1[nt * 8 + i2];
            float e0 = k0.x ? 0.f : __expf(acc[nt][0] * 0.125f - rm0);
            float e1 = k0.y ? 0.f : __expf(acc[nt][1] * 0.125f - rm0);
            float e2 = k1.x ? 0.f : __expf(acc[nt][2] * 0.125f - rm1);
            float e3 = k1.y ? 0.f : __expf(acc[nt][3] * 0.125f - rm1);
            s0 += e0 + e1;
            s1 += e2 + e3;
            acc[nt][0] = e0 * inv0;
            acc[nt][1] = e1 * inv0;
            acc[nt][2] = e2 * inv1;
            acc[nt][3] = e3 * inv1;
        }
        s0 += __shfl_xor_sync(0xffffffffu, s0, 1);
        s0 += __shfl_xor_sync(0xffffffffu, s0, 2);
        s1 += __shfl_xor_sync(0xffffffffu, s1, 1);
        s1 += __shfl_xor_sync(0xffffffffu, s1, 2);
        se0 += s0;
        se1 += s1;

        if (write_w) {
            #pragma unroll
            for (int nt = 0; nt < 16; nt++) {
                *(float2*)&wrow0[st * 128 + nt * 8 + i2] = make_float2(acc[nt][0], acc[nt][1]);
                *(float2*)&wrow1[st * 128 + nt * 8 + i2] = make_float2(acc[nt][2], acc[nt][3]);
            }
        }
        #pragma unroll
        for (int j = 0; j < 8; j++) {
            uint32_t ph[4], pl[4];
            pack2(acc[2 * j][0],     acc[2 * j][1],     ph[0], pl[0]);
            pack2(acc[2 * j][2],     acc[2 * j][3],     ph[1], pl[1]);
            pack2(acc[2 * j + 1][0], acc[2 * j + 1][1], ph[2], pl[2]);
            pack2(acc[2 * j + 1][2], acc[2 * j + 1][3], ph[3], pl[3]);
            uint32_t vh[8][2], vl[8][2];
            #pragma unroll
            for (int bt = 0; bt < 4; bt++) {
                uint32_t vd = smV + ((j * 16 + tbrow) * QSTR + bt * 16 + tbcol8) * 2;
                ldsm4t(vd, vh[2 * bt][0], vh[2 * bt][1], vh[2 * bt + 1][0], vh[2 * bt + 1][1]);
                ldsm4t(vd + F_LO, vl[2 * bt][0], vl[2 * bt][1], vl[2 * bt + 1][0], vl[2 * bt + 1][1]);
            }
            #pragma unroll
            for (int ntv = 0; ntv < 8; ntv++) {
                mma_bf16(acco[ntv], ph, vh[ntv][0], vh[ntv][1]);
                mma_bf16(acco[ntv], ph, vl[ntv][0], vl[ntv][1]);
                mma_bf16(acco[ntv], pl, vh[ntv][0], vh[ntv][1]);
            }
        }
        __syncthreads();
    }

    // exact-O correction: acco accumulated with e*inv; exact O = acco/(inv*se)
    const float fac0 = (inv0 > 0.f && se0 > 0.f) ? 1.f / (inv0 * se0) : 0.f;
    const float fac1 = (inv1 > 0.f && se1 > 0.f) ? 1.f / (inv1 * se1) : 0.f;

    float* Ob = O + (size_t)b * Tt * EMBD + h * HEAD + (size_t)(m0 + trow) * EMBD;
    #pragma unroll
    for (int ntv = 0; ntv < 8; ntv++) {
        *(float2*)&Ob[ntv * 8 + i2] =
            make_float2(acco[ntv][0] * fac0, acco[ntv][1] * fac0);
        *(float2*)&Ob[8 * EMBD + ntv * 8 + i2] =
            make_float2(acco[ntv][2] * fac1, acco[ntv][3] * fac1);
    }
}

// ===========================================================================
extern "C" void kernel_launch(void* const* d_in, const int* in_sizes, int n_in,
                              void* d_out, int out_size)
{
    const float* x    = (const float*)d_in[0];
    const float* ctx  = (const float*)d_in[1];
    const int*   mask = (const int*)d_in[2];
    const float* WQ = (const float*)d_in[3];
    const float* WK = (const float*)d_in[4];
    const float* WV = (const float*)d_in[5];
    const float* WO = (const float*)d_in[6];
    float* out = (float*)d_out;

    float *qp, *kp, *vp, *op;
    cudaGetSymbolAddress((void**)&qp, g_Q);
    cudaGetSymbolAddress((void**)&kp, g_K);
    cudaGetSymbolAddress((void**)&vp, g_V);
    cudaGetSymbolAddress((void**)&op, g_O);

    const size_t merged_elems = (size_t)BTR * EMBD;
    const size_t weight_elems = (size_t)Bb * Hh * Tt * Tt;
    const int write_w = ((size_t)out_size >= merged_elems + weight_elems) ? 1 : 0;
    float* wt;
    if (write_w) {
        wt = out + merged_elems;
    } else {
        cudaGetSymbolAddress((void**)&wt, g_W);
    }

    const int SMEM_NT = 2 * STAGE_NT;   // 80 KB
    cudaFuncSetAttribute(mma_qkv, cudaFuncAttributeMaxDynamicSharedMemorySize, SMEM_NT);
    cudaFuncSetAttribute(mma_out, cudaFuncAttributeMaxDynamicSharedMemorySize, SMEM_NT);
    cudaFuncSetAttribute(fused_attn, cudaFuncAttributeMaxDynamicSharedMemorySize, FSMEM);

    // prep all operands to chunk-blocked bf16 hi/lo (full-line loads)
    dim3 gp(2048, 1, 6);
    prep_all<<<gp, 256>>>(x, ctx, WQ, WK, WV, WO);

    // Q/K/V projections (prepped operands, zero in-loop conversion)
    dim3 gqkv(EMBD / 128, BTR / 128, 3);
    mma_qkv<<<gqkv, 512, SMEM_NT>>>(qp, kp, vp);

    // fused attention (R8 two-phase + exact-O correction)
    dim3 gf(Tt / 128, Bb * Hh);
    fused_attn<<<gf, 256, FSMEM>>>(qp, kp, vp, mask, wt, op, write_w);

    // output projection (A fp32, B prepped)
    dim3 gout(EMBD / 128, BTR / 128);
    mma_out<<<gout, 512, SMEM_NT>>>(op, out);
}

// round 14
// speedup vs baseline: 1.1595x; 1.1123x over previous
#include <cuda_runtime.h>
#include <cuda_bf16.h>
#include <cstdint>

#define Bb   4
#define Tt   1024
#define EMBD 1024
#define Hh   16
#define HEAD 64
#define BTR  (Bb * Tt)
#define NEG_BIG (-1e30f)

static __device__ float g_Q[(size_t)BTR * EMBD];
static __device__ float g_K[(size_t)BTR * EMBD];
static __device__ float g_V[(size_t)BTR * EMBD];
static __device__ float g_O[(size_t)BTR * EMBD];
static __device__ float g_W[(size_t)Bb * Hh * Tt * Tt];

// ===========================================================================
// helpers
// ===========================================================================
__device__ __forceinline__ uint32_t smem_u32(const void* p) {
    uint32_t a;
    asm("{ .reg .u64 t; cvta.to.shared.u64 t, %1; cvt.u32.u64 %0, t; }" : "=r"(a) : "l"(p));
    return a;
}
__device__ __forceinline__ void ldsm4(uint32_t addr, uint32_t& r0, uint32_t& r1,
                                      uint32_t& r2, uint32_t& r3) {
    asm volatile("ldmatrix.sync.aligned.m8n8.x4.shared.b16 {%0,%1,%2,%3}, [%4];"
                 : "=r"(r0), "=r"(r1), "=r"(r2), "=r"(r3) : "r"(addr));
}
__device__ __forceinline__ void ldsm4t(uint32_t addr, uint32_t& r0, uint32_t& r1,
                                       uint32_t& r2, uint32_t& r3) {
    asm volatile("ldmatrix.sync.aligned.m8n8.x4.trans.shared.b16 {%0,%1,%2,%3}, [%4];"
                 : "=r"(r0), "=r"(r1), "=r"(r2), "=r"(r3) : "r"(addr));
}
__device__ __forceinline__ void mma_bf16(float (&d)[4], const uint32_t (&a)[4],
                                         uint32_t b0, uint32_t b1) {
    asm volatile("mma.sync.aligned.m16n8k16.row.col.f32.bf16.bf16.f32 "
                 "{%0,%1,%2,%3},{%4,%5,%6,%7},{%8,%9},{%0,%1,%2,%3};"
                 : "+f"(d[0]), "+f"(d[1]), "+f"(d[2]), "+f"(d[3])
                 : "r"(a[0]), "r"(a[1]), "r"(a[2]), "r"(a[3]), "r"(b0), "r"(b1));
}
__device__ __forceinline__ void cvt_hilo(float4 v, uint2& hi, uint2& lo) {
    __nv_bfloat162 h0 = __floats2bfloat162_rn(v.x, v.y);
    __nv_bfloat162 h1 = __floats2bfloat162_rn(v.z, v.w);
    float rx = v.x - __bfloat162float(h0.x);
    float ry = v.y - __bfloat162float(h0.y);
    float rz = v.z - __bfloat162float(h1.x);
    float rw = v.w - __bfloat162float(h1.y);
    __nv_bfloat162 l0 = __floats2bfloat162_rn(rx, ry);
    __nv_bfloat162 l1 = __floats2bfloat162_rn(rz, rw);
    hi = make_uint2(*(uint32_t*)&h0, *(uint32_t*)&h1);
    lo = make_uint2(*(uint32_t*)&l0, *(uint32_t*)&l1);
}
__device__ __forceinline__ void pack2(float x, float y, uint32_t& h, uint32_t& l) {
    __nv_bfloat162 hh = __floats2bfloat162_rn(x, y);
    float rx = x - __bfloat162float(hh.x);
    float ry = y - __bfloat162float(hh.y);
    __nv_bfloat162 ll = __floats2bfloat162_rn(rx, ry);
    h = *(uint32_t*)&hh;
    l = *(uint32_t*)&ll;
}

// ===========================================================================
// NT GEMM (C = A * B^T) — exact R8 version. 128x128 block, BK=32,
// 512 threads / 16 warps, bf16 hi/lo 3-pass, fp32 in/out.
// ===========================================================================
#define STR_K  40
#define A_HI_O 0
#define A_LO_O 10240
#define B_HI_O 20480
#define B_LO_O 30720
#define STAGE_NT 40960

__device__ __forceinline__ void nt_body(const float* __restrict__ Ab,
                                        const float* __restrict__ Bp,
                                        float* __restrict__ Cb, char* sm,
                                        int m0, int n0)
{
    const int tid = threadIdx.x, lane = tid & 31, wid = tid >> 5;
    const int NC = EMBD / 32;

    float acc[2][4][4] = {};
    float4 la[2], lb[2];

    {
        #pragma unroll
        for (int i = 0; i < 2; i++) {
            int seg = tid + i * 512, row = seg >> 3, c4 = (seg & 7) << 2;
            la[i] = *(const float4*)&Ab[(size_t)(m0 + row) * EMBD + c4];
            lb[i] = *(const float4*)&Bp[(size_t)(n0 + row) * EMBD + c4];
        }
        #pragma unroll
        for (int i = 0; i < 2; i++) {
            int seg = tid + i * 512, row = seg >> 3, c4 = (seg & 7) << 2;
            uint2 h, l;
            cvt_hilo(la[i], h, l);
            uint32_t off = (uint32_t)(row * STR_K + c4) * 2;
            *(uint2*)(sm + A_HI_O + off) = h;
            *(uint2*)(sm + A_LO_O + off) = l;
            cvt_hilo(lb[i], h, l);
            *(uint2*)(sm + B_HI_O + off) = h;
            *(uint2*)(sm + B_LO_O + off) = l;
        }
    }
    __syncthreads();

    const int wm = wid >> 2, wn = wid & 3;
    const int arow = lane & 15, acol8 = (lane >> 4) << 3;
    const int brow = (lane & 7) + ((lane >> 4) << 3), bcol8 = ((lane >> 3) & 1) << 3;
    const uint32_t sb0 = smem_u32(sm);

    for (int c = 0; c < NC; c++) {
        if (c + 1 < NC) {
            int k0n = (c + 1) * 32;
            #pragma unroll
            for (int i = 0; i < 2; i++) {
                int seg = tid + i * 512, row = seg >> 3, c4 = (seg & 7) << 2;
                la[i] = *(const float4*)&Ab[(size_t)(m0 + row) * EMBD + k0n + c4];
                lb[i] = *(const float4*)&Bp[(size_t)(n0 + row) * EMBD + k0n + c4];
            }
        }
        const uint32_t sbase = sb0 + (c & 1) * STAGE_NT;
        #pragma unroll
        for (int ks = 0; ks < 2; ks++) {
            const int k0 = ks * 16;
            uint32_t ah[2][4], al[2][4];
            #pragma unroll
            for (int mt = 0; mt < 2; mt++) {
                int r = wm * 32 + mt * 16 + arow;
                uint32_t ad = sbase + A_HI_O + (r * STR_K + k0 + acol8) * 2;
                ldsm4(ad, ah[mt][0], ah[mt][1], ah[mt][2], ah[mt][3]);
                ldsm4(ad + (A_LO_O - A_HI_O), al[mt][0], al[mt][1], al[mt][2], al[mt][3]);
            }
            uint32_t bh[4][2], bl[4][2];
            #pragma unroll
            for (int bt = 0; bt < 2; bt++) {
                int r = wn * 32 + bt * 16 + brow;
                uint32_t bd = sbase + B_HI_O + (r * STR_K + k0 + bcol8) * 2;
                ldsm4(bd, bh[2 * bt][0], bh[2 * bt][1], bh[2 * bt + 1][0], bh[2 * bt + 1][1]);
                ldsm4(bd + (B_LO_O - B_HI_O),
                      bl[2 * bt][0], bl[2 * bt][1], bl[2 * bt + 1][0], bl[2 * bt + 1][1]);
            }
            #pragma unroll
            for (int mt = 0; mt < 2; mt++)
                #pragma unroll
                for (int nt = 0; nt < 4; nt++) {
                    mma_bf16(acc[mt][nt], ah[mt], bh[nt][0], bh[nt][1]);
                    mma_bf16(acc[mt][nt], ah[mt], bl[nt][0], bl[nt][1]);
                    mma_bf16(acc[mt][nt], al[mt], bh[nt][0], bh[nt][1]);
                }
        }
        if (c + 1 < NC) {
            char* dst = sm + ((c + 1) & 1) * STAGE_NT;
            #pragma unroll
            for (int i = 0; i < 2; i++) {
                int seg = tid + i * 512, row = seg >> 3, c4 = (seg & 7) << 2;
                uint2 h, l;
                cvt_hilo(la[i], h, l);
                uint32_t off = (uint32_t)(row * STR_K + c4) * 2;
                *(uint2*)(dst + A_HI_O + off) = h;
                *(uint2*)(dst + A_LO_O + off) = l;
                cvt_hilo(lb[i], h, l);
                *(uint2*)(dst + B_HI_O + off) = h;
                *(uint2*)(dst + B_LO_O + off) = l;
            }
        }
        __syncthreads();
    }

    const int rofs = lane >> 2, cofs = (lane & 3) * 2;
    #pragma unroll
    for (int mt = 0; mt < 2; mt++)
        #pragma unroll
        for (int nt = 0; nt < 4; nt++) {
            int m = m0 + wm * 32 + mt * 16 + rofs;
            int n = n0 + wn * 32 + nt * 8 + cofs;
            *(float2*)&Cb[(size_t)m * EMBD + n] =
                make_float2(acc[mt][nt][0], acc[mt][nt][1]);
            *(float2*)&Cb[(size_t)(m + 8) * EMBD + n] =
                make_float2(acc[mt][nt][2], acc[mt][nt][3]);
        }
}

__global__ void __launch_bounds__(512)
mma_qkv(const float* __restrict__ x, const float* __restrict__ ctx,
        const float* __restrict__ WQ, const float* __restrict__ WK,
        const float* __restrict__ WV,
        float* __restrict__ qp, float* __restrict__ kp, float* __restrict__ vp)
{
    extern __shared__ __align__(16) char sm[];
    const int z = blockIdx.z;
    const float* Ab = (z == 0) ? x : ctx;
    const float* Bp = (z == 0) ? WQ : ((z == 1) ? WK : WV);
    float* Cb = (z == 0) ? qp : ((z == 1) ? kp : vp);
    nt_body(Ab, Bp, Cb, sm, blockIdx.y * 128, blockIdx.x * 128);
}

__global__ void __launch_bounds__(512)
mma_out(const float* __restrict__ A, const float* __restrict__ W,
        float* __restrict__ C)
{
    extern __shared__ __align__(16) char sm[];
    nt_body(A, W, C, sm, blockIdx.y * 128, blockIdx.x * 128);
}

// ===========================================================================
// Fused attention, 512 threads / 16 warps. Warp (wm, wn): wm = 16 t-rows,
// wn = 64 of 128 s-cols per K tile. Phase 1 hi-only stats (combined across
// wn via smem), phase 2 exact scores + weights + AV (O halves reduced in
// smem, exact-sum corrected).
// ===========================================================================
#define QSTR  72
#define F_LO  18432
#define FQ    0
#define FK0   36864
#define FK1   73728
#define FV0   110592
#define FV1   147456
#define FSMEM 184320

__device__ __forceinline__ void fill64(const float* __restrict__ src, char* dst, int tid) {
    #pragma unroll
    for (int i = 0; i < 4; i++) {
        int seg = tid + i * 512, row = seg >> 4, c4 = (seg & 15) << 2;
        float4 v = *(const float4*)&src[(size_t)row * EMBD + c4];
        uint2 h, l;
        cvt_hilo(v, h, l);
        uint32_t off = (uint32_t)(row * QSTR + c4) * 2;
        *(uint2*)(dst + off) = h;
        *(uint2*)(dst + F_LO + off) = l;
    }
}
__device__ __forceinline__ void fill64_hi(const float* __restrict__ src, char* dst, int tid) {
    #pragma unroll
    for (int i = 0; i < 4; i++) {
        int seg = tid + i * 512, row = seg >> 4, c4 = (seg & 15) << 2;
        float4 v = *(const float4*)&src[(size_t)row * EMBD + c4];
        __nv_bfloat162 h0 = __floats2bfloat162_rn(v.x, v.y);
        __nv_bfloat162 h1 = __floats2bfloat162_rn(v.z, v.w);
        uint32_t off = (uint32_t)(row * QSTR + c4) * 2;
        *(uint2*)(dst + off) = make_uint2(*(uint32_t*)&h0, *(uint32_t*)&h1);
    }
}

// 16 t-rows x 64 s-cols per warp (8 nt tiles), exact (bf16x3)
#define SCORE_TILE(accv, smK)                                                    \
    do {                                                                          \
        _Pragma("unroll")                                                         \
        for (int ks = 0; ks < 4; ks++) {                                          \
            uint32_t bh[8][2], bl[8][2];                                          \
            _Pragma("unroll")                                                     \
            for (int bp = 0; bp < 4; bp++) {                                      \
                uint32_t bd = (smK) + ((wn * 64 + bp * 16 + brow) * QSTR + ks * 16 + bcol8) * 2; \
                ldsm4(bd, bh[2 * bp][0], bh[2 * bp][1], bh[2 * bp + 1][0], bh[2 * bp + 1][1]); \
                ldsm4(bd + F_LO, bl[2 * bp][0], bl[2 * bp][1], bl[2 * bp + 1][0], bl[2 * bp + 1][1]); \
            }                                                                     \
            _Pragma("unroll")                                                     \
            for (int nt = 0; nt < 8; nt++) {                                      \
                mma_bf16(accv[nt], qh[ks], bh[nt][0], bh[nt][1]);                 \
                mma_bf16(accv[nt], qh[ks], bl[nt][0], bl[nt][1]);                 \
                mma_bf16(accv[nt], ql[ks], bh[nt][0], bh[nt][1]);                 \
            }                                                                     \
        }                                                                         \
    } while (0)

// hi-only variant (phase 1)
#define SCORE_TILE_HI(accv, smK)                                                 \
    do {                                                                          \
        _Pragma("unroll")                                                         \
        for (int ks = 0; ks < 4; ks++) {                                          \
            uint32_t bh[8][2];                                                    \
            _Pragma("unroll")                                                     \
            for (int bp = 0; bp < 4; bp++) {                                      \
                uint32_t bd = (smK) + ((wn * 64 + bp * 16 + brow) * QSTR + ks * 16 + bcol8) * 2; \
                ldsm4(bd, bh[2 * bp][0], bh[2 * bp][1], bh[2 * bp + 1][0], bh[2 * bp + 1][1]); \
            }                                                                     \
            _Pragma("unroll")                                                     \
            for (int nt = 0; nt < 8; nt++)                                        \
                mma_bf16(accv[nt], qh[ks], bh[nt][0], bh[nt][1]);                 \
        }                                                                         \
    } while (0)

__global__ void __launch_bounds__(512)
fused_attn(const float* __restrict__ Q, const float* __restrict__ K,
           const float* __restrict__ V, const int* __restrict__ mask,
           float* __restrict__ Wt, float* __restrict__ O, int write_w)
{
    extern __shared__ __align__(16) char sm[];
    const uint32_t sb = smem_u32(sm);
    const int tid = threadIdx.x, lane = tid & 31, w = tid >> 5;
    const int wm = w >> 1, wn = w & 1;
    const int z = blockIdx.y, b = z >> 4, h = z & 15;
    const int m0 = blockIdx.x * 128;

    const float* Qb = Q + (size_t)b * Tt * EMBD + h * HEAD;
    const float* Kb = K + (size_t)b * Tt * EMBD + h * HEAD;
    const float* Vb = V + (size_t)b * Tt * EMBD + h * HEAD;
    const int* mb = mask + (size_t)b * Tt * Tt + (size_t)m0 * Tt;

    const int g = lane >> 2, i2 = (lane & 3) << 1;
    const int arow = lane & 15, acol8 = (lane >> 4) << 3;
    const int brow = (lane & 7) + ((lane >> 4) << 3), bcol8 = ((lane >> 3) & 1) << 3;
    const int tbrow = (lane & 7) + (((lane >> 3) & 1) << 3), tbcol8 = (lane >> 4) << 3;

    fill64(Qb + (size_t)m0 * EMBD, sm + FQ, tid);
    fill64_hi(Kb, sm + FK0, tid);
    __syncthreads();

    uint32_t qh[4][4], ql[4][4];
    #pragma unroll
    for (int ks = 0; ks < 4; ks++) {
        uint32_t ad = sb + FQ + ((wm * 16 + arow) * QSTR + ks * 16 + acol8) * 2;
        ldsm4(ad, qh[ks][0], qh[ks][1], qh[ks][2], qh[ks][3]);
        ldsm4(ad + F_LO, ql[ks][0], ql[ks][1], ql[ks][2], ql[ks][3]);
    }

    const int trow = wm * 16 + g;     // local t row; +8 for second half

    // ---------------- phase 1: stats (hi-only, per s-half) ----------------
    float rm0 = -3.0e38f, rm1 = -3.0e38f, rs0 = 0.f, rs1 = 0.f;
    for (int st = 0; st < 8; st++) {
        if (st < 7) fill64_hi(Kb + (size_t)(st + 1) * 128 * EMBD,
                              sm + (((st + 1) & 1) ? FK1 : FK0), tid);
        float acc[8][4] = {};
        const uint32_t smK = sb + ((st & 1) ? FK1 : FK0);
        SCORE_TILE_HI(acc, smK);

        const int* mr0 = mb + (size_t)trow * Tt + st * 128 + wn * 64;
        const int* mr1 = mr0 + 8 * Tt;
        #pragma unroll
        for (int nt = 0; nt < 8; nt++) {
            int2 k0 = *(const int2*)&mr0[nt * 8 + i2];
            int2 k1 = *(const int2*)&mr1[nt * 8 + i2];
            acc[nt][0] = k0.x ? NEG_BIG : acc[nt][0] * 0.125f;
            acc[nt][1] = k0.y ? NEG_BIG : acc[nt][1] * 0.125f;
            acc[nt][2] = k1.x ? NEG_BIG : acc[nt][2] * 0.125f;
            acc[nt][3] = k1.y ? NEG_BIG : acc[nt][3] * 0.125f;
        }
        float t0 = -3.0e38f, t1 = -3.0e38f;
        #pragma unroll
        for (int nt = 0; nt < 8; nt++) {
            t0 = fmaxf(t0, fmaxf(acc[nt][0], acc[nt][1]));
            t1 = fmaxf(t1, fmaxf(acc[nt][2], acc[nt][3]));
        }
        t0 = fmaxf(t0, __shfl_xor_sync(0xffffffffu, t0, 1));
        t0 = fmaxf(t0, __shfl_xor_sync(0xffffffffu, t0, 2));
        t1 = fmaxf(t1, __shfl_xor_sync(0xffffffffu, t1, 1));
        t1 = fmaxf(t1, __shfl_xor_sync(0xffffffffu, t1, 2));
        float nm0 = fmaxf(rm0, t0), nm1 = fmaxf(rm1, t1);
        float s0 = 0.f, s1 = 0.f;
        #pragma unroll
        for (int nt = 0; nt < 8; nt++) {
            s0 += __expf(acc[nt][0] - nm0) + __expf(acc[nt][1] - nm0);
            s1 += __expf(acc[nt][2] - nm1) + __expf(acc[nt][3] - nm1);
        }
        s0 += __shfl_xor_sync(0xffffffffu, s0, 1);
        s0 += __shfl_xor_sync(0xffffffffu, s0, 2);
        s1 += __shfl_xor_sync(0xffffffffu, s1, 1);
        s1 += __shfl_xor_sync(0xffffffffu, s1, 2);
        rs0 = rs0 * __expf(rm0 - nm0) + s0;  rm0 = nm0;
        rs1 = rs1 * __expf(rm1 - nm1) + s1;  rm1 = nm1;
        __syncthreads();
    }

    // combine the two s-halves (disjoint ranges -> exact combine)
    float* msm = (float*)(sm + FQ);          // [2][128]
    float* ssm = msm + 256;                  // [2][128]
    if ((lane & 3) == 0) {
        msm[wn * 128 + trow] = rm0;      ssm[wn * 128 + trow] = rs0;
        msm[wn * 128 + trow + 8] = rm1;  ssm[wn * 128 + trow + 8] = rs1;
    }
    __syncthreads();
    {
        float ma = msm[trow],        mbv = msm[128 + trow];
        float sa = ssm[trow],        sbv = ssm[128 + trow];
        float mc = fmaxf(ma, mbv);
        rs0 = sa * __expf(ma - mc) + sbv * __expf(mbv - mc);
        rm0 = mc;
        ma = msm[trow + 8];  mbv = msm[128 + trow + 8];
        sa = ssm[trow + 8];  sbv = ssm[128 + trow + 8];
        mc = fmaxf(ma, mbv);
        rs1 = sa * __expf(ma - mc) + sbv * __expf(mbv - mc);
        rm1 = mc;
    }
    const float inv0 = (rm0 <= -1e29f) ? 0.f : 1.f / rs0;
    const float inv1 = (rm1 <= -1e29f) ? 0.f : 1.f / rs1;

    // ---------------- phase 2: exact scores + weights + AV ----------------
    __syncthreads();
    fill64(Kb, sm + FK0, tid);
    fill64(Vb, sm + FV0, tid);
    __syncthreads();

    float acco[8][4] = {};
    float se0 = 0.f, se1 = 0.f;
    float* wrow0 = Wt + (size_t)z * Tt * Tt + (size_t)(m0 + trow) * Tt + wn * 64;
    float* wrow1 = wrow0 + 8 * Tt;

    for (int st = 0; st < 8; st++) {
        if (st < 7) {
            const int nb = (st + 1) & 1;
            fill64(Kb + (size_t)(st + 1) * 128 * EMBD, sm + (nb ? FK1 : FK0), tid);
            fill64(Vb + (size_t)(st + 1) * 128 * EMBD, sm + (nb ? FV1 : FV0), tid);
        }
        float acc[8][4] = {};
        const uint32_t smK = sb + ((st & 1) ? FK1 : FK0);
        const uint32_t smV = sb + ((st & 1) ? FV1 : FV0);
        SCORE_TILE(acc, smK);

        const int* mr0 = mb + (size_t)trow * Tt + st * 128 + wn * 64;
        const int* mr1 = mr0 + 8 * Tt;
        float s0 = 0.f, s1 = 0.f;
        #pragma unroll
        for (int nt = 0; nt < 8; nt++) {
            int2 k0 = *(const int2*)&mr0[nt * 8 + i2];
            int2 k1 = *(const int2*)&mr1[nt * 8 + i2];
            float e0 = k0.x ? 0.f : __expf(acc[nt][0] * 0.125f - rm0);
            float e1 = k0.y ? 0.f : __expf(acc[nt][1] * 0.125f - rm0);
            float e2 = k1.x ? 0.f : __expf(acc[nt][2] * 0.125f - rm1);
            float e3 = k1.y ? 0.f : __expf(acc[nt][3] * 0.125f - rm1);
            s0 += e0 + e1;
            s1 += e2 + e3;
            acc[nt][0] = e0 * inv0;
            acc[nt][1] = e1 * inv0;
            acc[nt][2] = e2 * inv1;
            acc[nt][3] = e3 * inv1;
        }
        s0 += __shfl_xor_sync(0xffffffffu, s0, 1);
        s0 += __shfl_xor_sync(0xffffffffu, s0, 2);
        s1 += __shfl_xor_sync(0xffffffffu, s1, 1);
        s1 += __shfl_xor_sync(0xffffffffu, s1, 2);
        se0 += s0;
        se1 += s1;

        if (write_w) {
            #pragma unroll
            for (int nt = 0; nt < 8; nt++) {
                *(float2*)&wrow0[st * 128 + nt * 8 + i2] = make_float2(acc[nt][0], acc[nt][1]);
                *(float2*)&wrow1[st * 128 + nt * 8 + i2] = make_float2(acc[nt][2], acc[nt][3]);
            }
        }
        // AV over this warp's 64 s-rows of V
        #pragma unroll
        for (int j = 0; j < 4; j++) {
            uint32_t ph[4], pl[4];
            pack2(acc[2 * j][0],     acc[2 * j][1],     ph[0], pl[0]);
            pack2(acc[2 * j][2],     acc[2 * j][3],     ph[1], pl[1]);
            pack2(acc[2 * j + 1][0], acc[2 * j + 1][1], ph[2], pl[2]);
            pack2(acc[2 * j + 1][2], acc[2 * j + 1][3], ph[3], pl[3]);
            uint32_t vh[8][2], vl[8][2];
            #pragma unroll
            for (int bt = 0; bt < 4; bt++) {
                uint32_t vd = smV + ((wn * 64 + j * 16 + tbrow) * QSTR + bt * 16 + tbcol8) * 2;
                ldsm4t(vd, vh[2 * bt][0], vh[2 * bt][1], vh[2 * bt + 1][0], vh[2 * bt + 1][1]);
                ldsm4t(vd + F_LO, vl[2 * bt][0], vl[2 * bt][1], vl[2 * bt + 1][0], vl[2 * bt + 1][1]);
            }
            #pragma unroll
            for (int ntv = 0; ntv < 8; ntv++) {
                mma_bf16(acco[ntv], ph, vh[ntv][0], vh[ntv][1]);
                mma_bf16(acco[ntv], ph, vl[ntv][0], vl[ntv][1]);
                mma_bf16(acco[ntv], pl, vh[ntv][0], vh[ntv][1]);
            }
        }
        __syncthreads();
    }

    // combine exact sums across wn
    float* sesm = (float*)(sm + FQ + 2048);   // [2][128]
    if ((lane & 3) == 0) {
        sesm[wn * 128 + trow] = se0;
        sesm[wn * 128 + trow + 8] = se1;
    }
    __syncthreads();
    se0 = sesm[trow] + sesm[128 + trow];
    se1 = sesm[trow + 8] + sesm[128 + trow + 8];
    const float fac0 = (inv0 > 0.f && se0 > 0.f) ? 1.f / (inv0 * se0) : 0.f;
    const float fac1 = (inv1 > 0.f && se1 > 0.f) ? 1.f / (inv1 * se1) : 0.f;

    // reduce O halves across wn via smem (reuse K tile region), then store
    float* osm = (float*)(sm + FK0);          // 128 x 64 fp32 = 32 KB
    if (wn == 0) {
        #pragma unroll
        for (int ntv = 0; ntv < 8; ntv++) {
            *(float2*)&osm[trow * 64 + ntv * 8 + i2] =
                make_float2(acco[ntv][0], acco[ntv][1]);
            *(float2*)&osm[(trow + 8) * 64 + ntv * 8 + i2] =
                make_float2(acco[ntv][2], acco[ntv][3]);
        }
    }
    __syncthreads();
    if (wn == 1) {
        float* Ob = O + (size_t)b * Tt * EMBD + h * HEAD + (size_t)(m0 + trow) * EMBD;
        #pragma unroll
        for (int ntv = 0; ntv < 8; ntv++) {
            float2 p0 = *(const float2*)&osm[trow * 64 + ntv * 8 + i2];
            float2 p1 = *(const float2*)&osm[(trow + 8) * 64 + ntv * 8 + i2];
            *(float2*)&Ob[ntv * 8 + i2] =
                make_float2((acco[ntv][0] + p0.x) * fac0, (acco[ntv][1] + p0.y) * fac0);
            *(float2*)&Ob[8 * EMBD + ntv * 8 + i2] =
                make_float2((acco[ntv][2] + p1.x) * fac1, (acco[ntv][3] + p1.y) * fac1);
        }
    }
}

// ===========================================================================
extern "C" void kernel_launch(void* const* d_in, const int* in_sizes, int n_in,
                              void* d_out, int out_size)
{
    const float* x    = (const float*)d_in[0];
    const float* ctx  = (const float*)d_in[1];
    const int*   mask = (const int*)d_in[2];
    const float* WQ = (const float*)d_in[3];
    const float* WK = (const float*)d_in[4];
    const float* WV = (const float*)d_in[5];
    const float* WO = (const float*)d_in[6];
    float* out = (float*)d_out;

    float *qp, *kp, *vp, *op;
    cudaGetSymbolAddress((void**)&qp, g_Q);
    cudaGetSymbolAddress((void**)&kp, g_K);
    cudaGetSymbolAddress((void**)&vp, g_V);
    cudaGetSymbolAddress((void**)&op, g_O);

    const size_t merged_elems = (size_t)BTR * EMBD;
    const size_t weight_elems = (size_t)Bb * Hh * Tt * Tt;
    const int write_w = ((size_t)out_size >= merged_elems + weight_elems) ? 1 : 0;
    float* wt;
    if (write_w) {
        wt = out + merged_elems;
    } else {
        cudaGetSymbolAddress((void**)&wt, g_W);
    }

    const int SMEM_NT = 2 * STAGE_NT;   // 80 KB
    cudaFuncSetAttribute(mma_qkv, cudaFuncAttributeMaxDynamicSharedMemorySize, SMEM_NT);
    cudaFuncSetAttribute(mma_out, cudaFuncAttributeMaxDynamicSharedMemorySize, SMEM_NT);
    cudaFuncSetAttribute(fused_attn, cudaFuncAttributeMaxDynamicSharedMemorySize, FSMEM);

    // Q/K/V projections (R8 proven)
    dim3 gqkv(EMBD / 128, BTR / 128, 3);
    mma_qkv<<<gqkv, 512, SMEM_NT>>>(x, ctx, WQ, WK, WV, qp, kp, vp);

    // fused attention, 512 threads / 16 warps
    dim3 gf(Tt / 128, Bb * Hh);
    fused_attn<<<gf, 512, FSMEM>>>(qp, kp, vp, mask, wt, op, write_w);

    // output projection (R8 proven)
    dim3 gout(EMBD / 128, BTR / 128);
    mma_out<<<gout, 512, SMEM_NT>>>(op, WO, out);
}